// round 14
// baseline (speedup 1.0000x reference)
#include <cuda_runtime.h>
#include <math_constants.h>

// Until: out[b,t,x] = min(phi[b,t,x], max(psi[b,t,x], out[b,t-1,x])), out[-1] = -1e6.
// Single-pass chained scan (decoupled lookback). Monoid f(v)=min(A,max(B,v)):
//   compose (later∘earlier): A' = min(A2, max(B2, A1)), B' = max(B1, B2).
// R14: R13 + ONE-SHOT 16B probe — AGG and PRE live in a single ulonglong2,
// so every lookback hop is exactly one L2 round trip (ld.volatile.v2.u64).

#define B_   64
#define T_   8192
#define X_   32
#define TC_  256                // time steps per chunk
#define C_   (T_ / TC_)         // 32 chunks per batch
#define NB_  (B_ * C_)          // 2048 blocks
#define SL_  32                 // t-slices per block
#define PT_  (TC_ / SL_)        // 8 steps per thread
#define NW_  8                  // warps per block == lookback window size
#define SPW_ (SL_ / NW_)        // 4 slices per warp
#define LARGE_ 1.0e6f

typedef unsigned long long u64;

// one 16B record per (chunk, x): {pk(tag, A_or_P), pk(tag, B)}
__device__ ulonglong2 g_ABpk[NB_ * X_];
__device__ int g_ticket;          // never reset; epoch = ticket / NB_

__device__ __forceinline__ u64 pk(int tag, float v) {
    return ((u64)(unsigned)tag << 32) | (u64)__float_as_uint(v);
}

__device__ __forceinline__ void st_v2_vol(ulonglong2* p, u64 a, u64 b) {
    asm volatile("st.volatile.global.v2.u64 [%0], {%1, %2};"
                 :: "l"(p), "l"(a), "l"(b) : "memory");
}

__device__ __forceinline__ ulonglong2 ld_v2_vol(const ulonglong2* p) {
    ulonglong2 r;
    asm volatile("ld.volatile.global.v2.u64 {%0, %1}, [%2];"
                 : "=l"(r.x), "=l"(r.y) : "l"(p) : "memory");
    return r;
}

__global__ void __launch_bounds__(256, 6) until_scan(const float* __restrict__ phi,
                                                     const float* __restrict__ psi,
                                                     float* __restrict__ out) {
    __shared__ float sA[SL_][X_];     // per-slice aggregate A
    __shared__ float sB[SL_][X_];     // per-slice aggregate B
    __shared__ float sWA[NW_][X_];    // per-warp fold of its 4 slices
    __shared__ float sWB[NW_][X_];
    __shared__ float sGC[NW_][X_];    // carry entering each warp's slice group
    __shared__ float wLA[NW_][X_];    // lookback window payload (A or P)
    __shared__ float wLB[NW_][X_];    // lookback window payload (B)
    __shared__ int   wSt[NW_][X_];    // per-lane status: 1 = PRE, 0 = AGG
    __shared__ float sFA[X_];         // block aggregate A
    __shared__ float sFB[X_];         // block aggregate B
    __shared__ int   s_done;
    __shared__ int   s_tic;

    const int tid = threadIdx.x;
    if (tid == 0) s_tic = atomicAdd(&g_ticket, 1);
    __syncthreads();
    const int traw = s_tic;
    const int e    = traw >> 11;          // epoch (NB_ = 2048)
    const int v    = traw & (NB_ - 1);
    const int b    = v % B_;              // breadth-first over chunks
    const int c    = v / B_;
    const int bc   = b * C_ + c;
    const int FLAG_AGG = 2 * e + 1;
    const int FLAG_PRE = 2 * e + 2;

    const int xg   = tid & 7;             // float4 group along x
    const int xq   = xg * 4;
    const int s    = tid >> 3;            // slice 0..31
    const int w    = tid >> 5;            // warp 0..7
    const int lane = tid & 31;

    const size_t base = (size_t)b * T_ * X_ + (size_t)(c * TC_ + s * PT_) * X_ + xq;
    const float4* pp = (const float4*)(phi + base);
    const float4* qq = (const float4*)(psi + base);

    // ---------- phase 1: streaming slice aggregate (lines land in L2) ----------
    float4 A  = make_float4( CUDART_INF_F,  CUDART_INF_F,  CUDART_INF_F,  CUDART_INF_F);
    float4 Bc = make_float4(-CUDART_INF_F, -CUDART_INF_F, -CUDART_INF_F, -CUDART_INF_F);
#pragma unroll
    for (int i = 0; i < PT_; i++) {
        float4 p = pp[i * (X_ / 4)];
        float4 q = qq[i * (X_ / 4)];
        A.x = fminf(p.x, fmaxf(q.x, A.x));  Bc.x = fmaxf(q.x, Bc.x);
        A.y = fminf(p.y, fmaxf(q.y, A.y));  Bc.y = fmaxf(q.y, Bc.y);
        A.z = fminf(p.z, fmaxf(q.z, A.z));  Bc.z = fmaxf(q.z, Bc.z);
        A.w = fminf(p.w, fmaxf(q.w, A.w));  Bc.w = fmaxf(q.w, Bc.w);
    }
    sA[s][xq + 0] = A.x;  sA[s][xq + 1] = A.y;  sA[s][xq + 2] = A.z;  sA[s][xq + 3] = A.w;
    sB[s][xq + 0] = Bc.x; sB[s][xq + 1] = Bc.y; sB[s][xq + 2] = Bc.z; sB[s][xq + 3] = Bc.w;
    __syncwarp();   // slices 4w..4w+3 are written by warp w's own threads

    // ---------- fold level 1: warp w folds its 4 slices (lane = x) ----------
    {
        float wA =  CUDART_INF_F;
        float wB = -CUDART_INF_F;
#pragma unroll
        for (int j = 0; j < SPW_; j++) {
            const int sl = w * SPW_ + j;
            wA = fminf(sA[sl][lane], fmaxf(sB[sl][lane], wA));
            wB = fmaxf(sB[sl][lane], wB);
        }
        sWA[w][lane] = wA;
        sWB[w][lane] = wB;
    }
    __syncthreads();

    // ---------- warp 0: fold level 2 + publish AGG (one 16B store) ----------
    if (tid < 32) {
        const int x = tid;
        float Ab =  CUDART_INF_F;
        float Bb = -CUDART_INF_F;
#pragma unroll
        for (int j = 0; j < NW_; j++) {
            Ab = fminf(sWA[j][x], fmaxf(sWB[j][x], Ab));
            Bb = fmaxf(sWB[j][x], Bb);
        }
        sFA[x] = Ab;
        sFB[x] = Bb;
        // chunk 0 never publishes AGG -> lookback can't cross batch boundary
        if (c > 0) {
            st_v2_vol(&g_ABpk[bc * X_ + x], pk(FLAG_AGG, Ab), pk(FLAG_AGG, Bb));
        }
    }
    __syncthreads();

    // ---------- parallel-window lookback: 8 warps x 1 predecessor per round ----------
    float vin = -LARGE_;                  // meaningful in warp-0 lanes
    if (c > 0) {
        const int batch_lo = b * C_;      // chunk 0 of this batch (always reaches PRE)
        int hi = bc - 1;
        float accA =  CUDART_INF_F;       // warp-0 per-lane accumulators
        float accB = -CUDART_INF_F;
        int found = 0;
        while (true) {
            const int j = hi - w;         // warp w probes predecessor j (per-lane x)
            if (j >= batch_lo) {
                const ulonglong2* gp = &g_ABpk[j * X_ + lane];
                int st; float av, bv;
                while (true) {
                    ulonglong2 r = ld_v2_vol(gp);
                    const int t0 = (int)(r.x >> 32);
                    if (t0 == FLAG_PRE) {                 // resolved prefix
                        st = 1; av = __uint_as_float((unsigned)r.x); bv = -CUDART_INF_F;
                        break;
                    }
                    if (t0 == FLAG_AGG && (int)(r.y >> 32) == FLAG_AGG) {
                        st = 0; av = __uint_as_float((unsigned)r.x);
                        bv = __uint_as_float((unsigned)r.y);
                        break;
                    }
                    // not published yet, or torn AGG->PRE overwrite: retry
                }
                wLA[w][lane] = av;
                wLB[w][lane] = bv;
                wSt[w][lane] = st;
            }
            __syncthreads();
            if (tid < 32) {
                const int x = tid;
                if (!found) {
#pragma unroll
                    for (int k = 0; k < NW_; k++) {
                        if (hi - k < batch_lo) break;     // below batch floor: stop
                        if (wSt[k][x]) {                  // PRE: resolve this lane
                            vin = fminf(accA, fmaxf(accB, wLA[k][x]));
                            found = 1;
                            break;
                        }
                        accA = fminf(accA, fmaxf(accB, wLA[k][x]));
                        accB = fmaxf(accB, wLB[k][x]);
                    }
                }
                int all = __all_sync(0xffffffffu, found);
                if (x == 0) s_done = all;
            }
            __syncthreads();
            if (s_done) break;
            hi -= NW_;
        }
    }

    // ---------- warp 0: publish PRE first (one 16B store), fill carries ----------
    if (tid < 32) {
        const int x = tid;
        float pre = fminf(sFA[x], fmaxf(sFB[x], vin));
        st_v2_vol(&g_ABpk[bc * X_ + x], pk(FLAG_PRE, pre), pk(FLAG_PRE, 0.0f));

        float g = vin;
#pragma unroll
        for (int j = 0; j < NW_; j++) {
            sGC[j][x] = g;
            g = fminf(sWA[j][x], fmaxf(sWB[j][x], g));
        }
    }
    __syncthreads();

    // ---------- per-thread slice carry (walk <=3 slices from warp-group carry) ----------
    float v0 = sGC[w][xq + 0];
    float v1 = sGC[w][xq + 1];
    float v2 = sGC[w][xq + 2];
    float v3 = sGC[w][xq + 3];
    for (int j = w * SPW_; j < s; j++) {
        v0 = fminf(sA[j][xq + 0], fmaxf(sB[j][xq + 0], v0));
        v1 = fminf(sA[j][xq + 1], fmaxf(sB[j][xq + 1], v1));
        v2 = fminf(sA[j][xq + 2], fmaxf(sB[j][xq + 2], v2));
        v3 = fminf(sA[j][xq + 3], fmaxf(sB[j][xq + 3], v3));
    }
    float4 vc = make_float4(v0, v1, v2, v3);

    // ---------- phase 2: reload (L2 hits), apply carry, stream out ----------
    float4* oo = (float4*)(out + base);
#pragma unroll
    for (int i = 0; i < PT_; i++) {
        float4 p = __ldcs(&pp[i * (X_ / 4)]);
        float4 q = __ldcs(&qq[i * (X_ / 4)]);
        vc.x = fminf(p.x, fmaxf(q.x, vc.x));
        vc.y = fminf(p.y, fmaxf(q.y, vc.y));
        vc.z = fminf(p.z, fmaxf(q.z, vc.z));
        vc.w = fminf(p.w, fmaxf(q.w, vc.w));
        __stcs(&oo[i * (X_ / 4)], vc);
    }
}

extern "C" void kernel_launch(void* const* d_in, const int* in_sizes, int n_in,
                              void* d_out, int out_size) {
    const float* phi = (const float*)d_in[0];
    const float* psi = (const float*)d_in[1];
    float* out = (float*)d_out;

    until_scan<<<NB_, 256>>>(phi, psi, out);
}

// round 15
// speedup vs baseline: 1.0054x; 1.0054x over previous
#include <cuda_runtime.h>
#include <math_constants.h>

// Until: out[b,t,x] = min(phi[b,t,x], max(psi[b,t,x], out[b,t-1,x])), out[-1] = -1e6.
// Single-pass chained scan (decoupled lookback). Monoid f(v)=min(A,max(B,v)):
//   compose (later∘earlier): A' = min(A2, max(B2, A1)), B' = max(B1, B2).
// R15: R14 body, but __launch_bounds__(256, 8) -> 8 CTAs/SM (~88% occ) to hide
// DRAM latency like the standalone streaming kernel (which hit 70% DRAM at
// occ 92%). Register pressure trimmed to help ptxas stay at 32 regs.

#define B_   64
#define T_   8192
#define X_   32
#define TC_  256                // time steps per chunk
#define C_   (T_ / TC_)         // 32 chunks per batch
#define NB_  (B_ * C_)          // 2048 blocks
#define SL_  32                 // t-slices per block
#define PT_  (TC_ / SL_)        // 8 steps per thread
#define NW_  8                  // warps per block == lookback window size
#define SPW_ (SL_ / NW_)        // 4 slices per warp
#define LARGE_ 1.0e6f

typedef unsigned long long u64;

// one 16B record per (chunk, x): {pk(tag, A_or_P), pk(tag, B)}
__device__ ulonglong2 g_ABpk[NB_ * X_];
__device__ int g_ticket;          // never reset; epoch = ticket / NB_

__device__ __forceinline__ u64 pk(int tag, float v) {
    return ((u64)(unsigned)tag << 32) | (u64)__float_as_uint(v);
}

__device__ __forceinline__ void st_v2_vol(ulonglong2* p, u64 a, u64 b) {
    asm volatile("st.volatile.global.v2.u64 [%0], {%1, %2};"
                 :: "l"(p), "l"(a), "l"(b) : "memory");
}

__device__ __forceinline__ ulonglong2 ld_v2_vol(const ulonglong2* p) {
    ulonglong2 r;
    asm volatile("ld.volatile.global.v2.u64 {%0, %1}, [%2];"
                 : "=l"(r.x), "=l"(r.y) : "l"(p) : "memory");
    return r;
}

__global__ void __launch_bounds__(256, 8) until_scan(const float* __restrict__ phi,
                                                     const float* __restrict__ psi,
                                                     float* __restrict__ out) {
    __shared__ float sA[SL_][X_];     // per-slice aggregate A
    __shared__ float sB[SL_][X_];     // per-slice aggregate B
    __shared__ float sWA[NW_][X_];    // per-warp fold of its 4 slices
    __shared__ float sWB[NW_][X_];
    __shared__ float sGC[NW_][X_];    // carry entering each warp's slice group
    __shared__ float wLA[NW_][X_];    // lookback window payload (A or P)
    __shared__ float wLB[NW_][X_];    // lookback window payload (B)
    __shared__ int   wSt[NW_][X_];    // per-lane status: 1 = PRE, 0 = AGG
    __shared__ float sFA[X_];         // block aggregate A
    __shared__ float sFB[X_];         // block aggregate B
    __shared__ int   s_done;
    __shared__ int   s_tic;

    const int tid = threadIdx.x;
    if (tid == 0) s_tic = atomicAdd(&g_ticket, 1);
    __syncthreads();
    const int traw = s_tic;
    const int e    = traw >> 11;          // epoch (NB_ = 2048)
    const int v    = traw & (NB_ - 1);
    const int b    = v % B_;              // breadth-first over chunks
    const int c    = v / B_;
    const int bc   = b * C_ + c;
    const int FLAG_AGG = 2 * e + 1;
    const int FLAG_PRE = 2 * e + 2;

    const int xg   = tid & 7;             // float4 group along x
    const int xq   = xg * 4;
    const int s    = tid >> 3;            // slice 0..31
    const int w    = tid >> 5;            // warp 0..7
    const int lane = tid & 31;

    // 32-bit element indexing off one base (all offsets < 16M float4s)
    const unsigned fbase = (unsigned)(b * (T_ * X_ / 4) + (c * TC_ + s * PT_) * (X_ / 4) + xg);
    const float4* pp = (const float4*)phi + fbase;
    const float4* qq = (const float4*)psi + fbase;

    // ---------- phase 1: streaming slice aggregate (lines land in L2) ----------
    float4 A  = make_float4( CUDART_INF_F,  CUDART_INF_F,  CUDART_INF_F,  CUDART_INF_F);
    float4 Bc = make_float4(-CUDART_INF_F, -CUDART_INF_F, -CUDART_INF_F, -CUDART_INF_F);
#pragma unroll
    for (int i = 0; i < PT_; i++) {
        float4 p = pp[i * (X_ / 4)];
        float4 q = qq[i * (X_ / 4)];
        A.x = fminf(p.x, fmaxf(q.x, A.x));  Bc.x = fmaxf(q.x, Bc.x);
        A.y = fminf(p.y, fmaxf(q.y, A.y));  Bc.y = fmaxf(q.y, Bc.y);
        A.z = fminf(p.z, fmaxf(q.z, A.z));  Bc.z = fmaxf(q.z, Bc.z);
        A.w = fminf(p.w, fmaxf(q.w, A.w));  Bc.w = fmaxf(q.w, Bc.w);
    }
    sA[s][xq + 0] = A.x;  sA[s][xq + 1] = A.y;  sA[s][xq + 2] = A.z;  sA[s][xq + 3] = A.w;
    sB[s][xq + 0] = Bc.x; sB[s][xq + 1] = Bc.y; sB[s][xq + 2] = Bc.z; sB[s][xq + 3] = Bc.w;
    __syncwarp();   // slices 4w..4w+3 are written by warp w's own threads

    // ---------- fold level 1: warp w folds its 4 slices (lane = x) ----------
    {
        float wA =  CUDART_INF_F;
        float wB = -CUDART_INF_F;
#pragma unroll
        for (int j = 0; j < SPW_; j++) {
            const int sl = w * SPW_ + j;
            wA = fminf(sA[sl][lane], fmaxf(sB[sl][lane], wA));
            wB = fmaxf(sB[sl][lane], wB);
        }
        sWA[w][lane] = wA;
        sWB[w][lane] = wB;
    }
    __syncthreads();

    // ---------- warp 0: fold level 2 + publish AGG (one 16B store) ----------
    if (tid < 32) {
        const int x = tid;
        float Ab =  CUDART_INF_F;
        float Bb = -CUDART_INF_F;
#pragma unroll
        for (int j = 0; j < NW_; j++) {
            Ab = fminf(sWA[j][x], fmaxf(sWB[j][x], Ab));
            Bb = fmaxf(sWB[j][x], Bb);
        }
        sFA[x] = Ab;
        sFB[x] = Bb;
        // chunk 0 never publishes AGG -> lookback can't cross batch boundary
        if (c > 0) {
            st_v2_vol(&g_ABpk[bc * X_ + x], pk(FLAG_AGG, Ab), pk(FLAG_AGG, Bb));
        }
    }
    __syncthreads();

    // ---------- parallel-window lookback: 8 warps x 1 predecessor per round ----------
    float vin = -LARGE_;                  // meaningful in warp-0 lanes
    if (c > 0) {
        const int batch_lo = b * C_;      // chunk 0 of this batch (always reaches PRE)
        int hi = bc - 1;
        float accA =  CUDART_INF_F;       // warp-0 per-lane accumulators
        float accB = -CUDART_INF_F;
        int found = 0;
        while (true) {
            const int j = hi - w;         // warp w probes predecessor j (per-lane x)
            if (j >= batch_lo) {
                const ulonglong2* gp = &g_ABpk[j * X_ + lane];
                int st; float av, bv;
                while (true) {
                    ulonglong2 r = ld_v2_vol(gp);
                    const int t0 = (int)(r.x >> 32);
                    if (t0 == FLAG_PRE) {                 // resolved prefix
                        st = 1; av = __uint_as_float((unsigned)r.x); bv = -CUDART_INF_F;
                        break;
                    }
                    if (t0 == FLAG_AGG && (int)(r.y >> 32) == FLAG_AGG) {
                        st = 0; av = __uint_as_float((unsigned)r.x);
                        bv = __uint_as_float((unsigned)r.y);
                        break;
                    }
                    // not published yet, or torn AGG->PRE overwrite: retry
                }
                wLA[w][lane] = av;
                wLB[w][lane] = bv;
                wSt[w][lane] = st;
            }
            __syncthreads();
            if (tid < 32) {
                const int x = tid;
                if (!found) {
#pragma unroll
                    for (int k = 0; k < NW_; k++) {
                        if (hi - k < batch_lo) break;     // below batch floor: stop
                        if (wSt[k][x]) {                  // PRE: resolve this lane
                            vin = fminf(accA, fmaxf(accB, wLA[k][x]));
                            found = 1;
                            break;
                        }
                        accA = fminf(accA, fmaxf(accB, wLA[k][x]));
                        accB = fmaxf(accB, wLB[k][x]);
                    }
                }
                int all = __all_sync(0xffffffffu, found);
                if (x == 0) s_done = all;
            }
            __syncthreads();
            if (s_done) break;
            hi -= NW_;
        }
    }

    // ---------- warp 0: publish PRE first (one 16B store), fill carries ----------
    if (tid < 32) {
        const int x = tid;
        float pre = fminf(sFA[x], fmaxf(sFB[x], vin));
        st_v2_vol(&g_ABpk[bc * X_ + x], pk(FLAG_PRE, pre), pk(FLAG_PRE, 0.0f));

        float g = vin;
#pragma unroll
        for (int j = 0; j < NW_; j++) {
            sGC[j][x] = g;
            g = fminf(sWA[j][x], fmaxf(sWB[j][x], g));
        }
    }
    __syncthreads();

    // ---------- per-thread slice carry (walk <=3 slices from warp-group carry) ----------
    float v0 = sGC[w][xq + 0];
    float v1 = sGC[w][xq + 1];
    float v2 = sGC[w][xq + 2];
    float v3 = sGC[w][xq + 3];
    for (int j = w * SPW_; j < s; j++) {
        v0 = fminf(sA[j][xq + 0], fmaxf(sB[j][xq + 0], v0));
        v1 = fminf(sA[j][xq + 1], fmaxf(sB[j][xq + 1], v1));
        v2 = fminf(sA[j][xq + 2], fmaxf(sB[j][xq + 2], v2));
        v3 = fminf(sA[j][xq + 3], fmaxf(sB[j][xq + 3], v3));
    }
    float4 vc = make_float4(v0, v1, v2, v3);

    // ---------- phase 2: reload (L2 hits), apply carry, stream out ----------
    float4* oo = (float4*)out + fbase;
#pragma unroll
    for (int i = 0; i < PT_; i++) {
        float4 p = __ldcs(&pp[i * (X_ / 4)]);
        float4 q = __ldcs(&qq[i * (X_ / 4)]);
        vc.x = fminf(p.x, fmaxf(q.x, vc.x));
        vc.y = fminf(p.y, fmaxf(q.y, vc.y));
        vc.z = fminf(p.z, fmaxf(q.z, vc.z));
        vc.w = fminf(p.w, fmaxf(q.w, vc.w));
        __stcs(&oo[i * (X_ / 4)], vc);
    }
}

extern "C" void kernel_launch(void* const* d_in, const int* in_sizes, int n_in,
                              void* d_out, int out_size) {
    const float* phi = (const float*)d_in[0];
    const float* psi = (const float*)d_in[1];
    float* out = (float*)d_out;

    until_scan<<<NB_, 256>>>(phi, psi, out);
}